// round 1
// baseline (speedup 1.0000x reference)
#include <cuda_runtime.h>
#include <math.h>

// Problem constants
#define B_       8
#define T_       1024
#define DIM_     512
#define H_       8
#define DK_      64
#define L_       32
#define DH_      512
#define THREE_DH 1536
#define NH_      64          // B_*H_
#define DOUT_    512
#define EPS_     1e-5f

// -------- scratch (static __device__; no runtime allocation) --------
__device__ float g_G[(size_t)8192 * 1536];   // qkv projection: row = b*T+t, col o in [0,1536)
                                             // [0,512)=q  [512,1024)=k(->exp'd)  [1024,1536)=v
__device__ float g_D[(size_t)4096 * 1024];   // pre-output: row = b*512 + (h*64+e), col t
__device__ float g_ctx[NH_ * DK_ * DK_];     // context[n][d][e]
__device__ float g_S[NH_ * T_];              // S[n][t]
__device__ float g_Psum[T_ * DK_];           // band-summed rel positions
__device__ float g_ksum[NH_ * DK_];          // softmax denominators
__device__ float g_bnsum[DK_];
__device__ float g_bnsumsq[DK_];
__device__ float g_bnscale[DK_];
__device__ float g_bnshift[DK_];

// ---------------------------------------------------------------
// Prep: Psum[t][d] = sum over valid band offsets of rel_positions,
// plus zeroing of all accumulators (required per graph replay).
// grid 1024 blocks x 64 threads
// ---------------------------------------------------------------
__global__ void __launch_bounds__(64) prep_kernel(const float* __restrict__ relpos) {
    const int t = blockIdx.x;
    const int d = threadIdx.x;
    int rlo = max(0, (L_ - 1) - t);
    int rhi = min(2 * L_ - 2, (T_ - 1) + (L_ - 1) - t);
    float s = 0.f;
    for (int r = rlo; r <= rhi; r++) s += relpos[r * DK_ + d];
    g_Psum[t * DK_ + d] = s;

    if (blockIdx.x < NH_) g_ksum[blockIdx.x * DK_ + d] = 0.f;
    if (blockIdx.x == 0) { g_bnsum[d] = 0.f; g_bnsumsq[d] = 0.f; }
}

// ---------------------------------------------------------------
// K1: G = x(8192x512) * Wqkv^T(512x1536)   (NT SGEMM, 128x128x16 tiles)
// grid (12, 64), 256 threads
// ---------------------------------------------------------------
__global__ void __launch_bounds__(256) qkv_gemm_kernel(const float* __restrict__ A,
                                                       const float* __restrict__ Bw) {
    __shared__ float As[16][128];
    __shared__ float Bs[16][128];
    const int bm = blockIdx.y * 128;
    const int bn = blockIdx.x * 128;
    const int tid = threadIdx.x;
    const int tm = tid >> 4, tn = tid & 15;
    const int K = 512;

    float acc[8][8];
#pragma unroll
    for (int i = 0; i < 8; i++)
#pragma unroll
        for (int j = 0; j < 8; j++) acc[i][j] = 0.f;

    for (int k0 = 0; k0 < K; k0 += 16) {
#pragma unroll
        for (int i = 0; i < 2; i++) {
            int idx = tid * 2 + i;          // 0..511
            int row = idx >> 2;             // 0..127
            int kc  = (idx & 3) * 4;        // 0,4,8,12
            float4 a = *(const float4*)(A + (size_t)(bm + row) * K + k0 + kc);
            As[kc + 0][row] = a.x; As[kc + 1][row] = a.y;
            As[kc + 2][row] = a.z; As[kc + 3][row] = a.w;
            float4 b = *(const float4*)(Bw + (size_t)(bn + row) * K + k0 + kc);
            Bs[kc + 0][row] = b.x; Bs[kc + 1][row] = b.y;
            Bs[kc + 2][row] = b.z; Bs[kc + 3][row] = b.w;
        }
        __syncthreads();
#pragma unroll
        for (int kk = 0; kk < 16; kk++) {
            float4 a0 = *(const float4*)&As[kk][tm * 8];
            float4 a1 = *(const float4*)&As[kk][tm * 8 + 4];
            float4 b0 = *(const float4*)&Bs[kk][tn * 8];
            float4 b1 = *(const float4*)&Bs[kk][tn * 8 + 4];
            float ra[8] = {a0.x, a0.y, a0.z, a0.w, a1.x, a1.y, a1.z, a1.w};
            float rb[8] = {b0.x, b0.y, b0.z, b0.w, b1.x, b1.y, b1.z, b1.w};
#pragma unroll
            for (int i = 0; i < 8; i++)
#pragma unroll
                for (int j = 0; j < 8; j++) acc[i][j] += ra[i] * rb[j];
        }
        __syncthreads();
    }
#pragma unroll
    for (int i = 0; i < 8; i++) {
        float* crow = g_G + (size_t)(bm + tm * 8 + i) * THREE_DH + bn + tn * 8;
#pragma unroll
        for (int j = 0; j < 8; j += 4) {
            float4 v = make_float4(acc[i][j], acc[i][j + 1], acc[i][j + 2], acc[i][j + 3]);
            *(float4*)(crow + j) = v;
        }
    }
}

// ---------------------------------------------------------------
// K2: in-place exp of k region + per-(n,d) denominators.
// No max-subtraction: k ~ N(0,1) for this problem; exp(k) <= ~250, exact in fp32.
// grid 256 = (n,chunk), 256 threads
// ---------------------------------------------------------------
__global__ void __launch_bounds__(256) ksoftmax_kernel() {
    const int n = blockIdx.x >> 2;
    const int chunk = blockIdx.x & 3;
    const int b = n >> 3, h = n & 7;
    const int d = threadIdx.x & 63;
    const int ts = threadIdx.x >> 6;
    const size_t base = (size_t)b * T_ * THREE_DH + DH_ + h * DK_ + d;

    float s = 0.f;
    for (int t = chunk * 256 + ts; t < chunk * 256 + 256; t += 4) {
        size_t idx = base + (size_t)t * THREE_DH;
        float e = __expf(g_G[idx]);
        g_G[idx] = e;
        s += e;
    }
    __shared__ float red[4][64];
    red[ts][d] = s;
    __syncthreads();
    if (ts == 0) {
        float tot = red[0][d] + red[1][d] + red[2][d] + red[3][d];
        atomicAdd(&g_ksum[n * DK_ + d], tot);
    }
}

// ---------------------------------------------------------------
// K3: context[n][d][e] = sum_t softmax(k)[d,t] * v[e,t]
// grid 64 (n), 256 threads; each thread 4x4 accumulators
// ---------------------------------------------------------------
__global__ void __launch_bounds__(256) context_kernel() {
    const int n = blockIdx.x;
    const int b = n >> 3, h = n & 7;
    __shared__ float sk[8][64];
    __shared__ float sv[8][64];
    __shared__ float krcp[64];
    const int tid = threadIdx.x;
    if (tid < 64) krcp[tid] = 1.f / g_ksum[n * DK_ + tid];
    __syncthreads();

    const int td = tid & 15, te = tid >> 4;
    float acc[4][4];
#pragma unroll
    for (int i = 0; i < 4; i++)
#pragma unroll
        for (int j = 0; j < 4; j++) acc[i][j] = 0.f;

    const size_t kbase = (size_t)b * T_ * THREE_DH + DH_ + h * DK_;
    const size_t vbase = kbase + DH_;

    for (int t0 = 0; t0 < T_; t0 += 8) {
#pragma unroll
        for (int i = 0; i < 2; i++) {
            int idx = tid * 2 + i;       // 0..511
            int tt = idx >> 6, ch = idx & 63;
            sk[tt][ch] = g_G[kbase + (size_t)(t0 + tt) * THREE_DH + ch] * krcp[ch];
            sv[tt][ch] = g_G[vbase + (size_t)(t0 + tt) * THREE_DH + ch];
        }
        __syncthreads();
#pragma unroll
        for (int tt = 0; tt < 8; tt++) {
            float ra[4], rb[4];
#pragma unroll
            for (int i = 0; i < 4; i++) ra[i] = sk[tt][td * 4 + i];
#pragma unroll
            for (int j = 0; j < 4; j++) rb[j] = sv[tt][te * 4 + j];
#pragma unroll
            for (int i = 0; i < 4; i++)
#pragma unroll
                for (int j = 0; j < 4; j++) acc[i][j] += ra[i] * rb[j];
        }
        __syncthreads();
    }
#pragma unroll
    for (int i = 0; i < 4; i++)
#pragma unroll
        for (int j = 0; j < 4; j++)
            g_ctx[(n * DK_ + td * 4 + i) * DK_ + te * 4 + j] = acc[i][j];
}

// ---------------------------------------------------------------
// K3b: S[n][t] = sum_d q[n,d,t]*Psum[t,d]; BN partial sums of rel = v*S
// grid 64 (n), 256 threads
// ---------------------------------------------------------------
__global__ void __launch_bounds__(256) s_bn_kernel() {
    const int n = blockIdx.x;
    const int b = n >> 3, h = n & 7;
    const int tid = threadIdx.x;
    const int w = tid >> 5, lane = tid & 31;
    __shared__ float S_sh[1024];
    const size_t qbase = (size_t)b * T_ * THREE_DH + h * DK_;

    for (int t = w; t < T_; t += 8) {
        const float* qrow = g_G + qbase + (size_t)t * THREE_DH;
        const float* prow = g_Psum + t * DK_;
        float v = qrow[lane] * prow[lane] + qrow[lane + 32] * prow[lane + 32];
#pragma unroll
        for (int o = 16; o > 0; o >>= 1) v += __shfl_xor_sync(0xffffffff, v, o);
        if (lane == 0) { S_sh[t] = v; g_S[n * T_ + t] = v; }
    }
    __syncthreads();

    const int e = tid & 63, ts = tid >> 6;
    const size_t vbase = (size_t)b * T_ * THREE_DH + 2 * DH_ + h * DK_ + e;
    float sum = 0.f, sq = 0.f;
    for (int t = ts; t < T_; t += 4) {
        float vv = g_G[vbase + (size_t)t * THREE_DH];
        float r = vv * S_sh[t];
        sum += r; sq += r * r;
    }
    __shared__ float red[4][64];
    red[ts][e] = sum;
    __syncthreads();
    if (ts == 0) atomicAdd(&g_bnsum[e], red[0][e] + red[1][e] + red[2][e] + red[3][e]);
    __syncthreads();
    red[ts][e] = sq;
    __syncthreads();
    if (ts == 0) atomicAdd(&g_bnsumsq[e], red[0][e] + red[1][e] + red[2][e] + red[3][e]);
}

// ---------------------------------------------------------------
// K4: finalize BN affine params. 1 block x 64 threads
// ---------------------------------------------------------------
__global__ void __launch_bounds__(64) bn_finalize_kernel(const float* __restrict__ gamma,
                                                         const float* __restrict__ beta) {
    const int e = threadIdx.x;
    const float cnt = (float)(NH_ * T_);
    float mu = g_bnsum[e] / cnt;
    float var = g_bnsumsq[e] / cnt - mu * mu;
    var = fmaxf(var, 0.f);
    float sc = gamma[e] * rsqrtf(var + EPS_);
    g_bnscale[e] = sc;
    g_bnshift[e] = beta[e] - mu * sc;
}

// ---------------------------------------------------------------
// K5a: D[b*512+h*64+e][t] = sum_d ctx[n][d][e]*q[n,d,t] + bn(v*S)
// grid 64 (n), 256 threads; warp w owns e = w*8..w*8+7, lanes over t
// ---------------------------------------------------------------
__global__ void __launch_bounds__(256) compute_d_kernel() {
    const int n = blockIdx.x;
    const int b = n >> 3, h = n & 7;
    const int tid = threadIdx.x;
    const int w = tid >> 5, lane = tid & 31;

    __shared__ float ctx_sh[64 * 64];
    __shared__ float q_sh[32 * 65];
    __shared__ float v_sh[32 * 65];
    __shared__ float S_sh[1024];
    __shared__ float sc_sh[64], sh_sh[64];

    for (int i = tid; i < 4096; i += 256) ctx_sh[i] = g_ctx[n * 4096 + i];
    for (int i = tid; i < 1024; i += 256) S_sh[i] = g_S[n * T_ + i];
    if (tid < 64) { sc_sh[tid] = g_bnscale[tid]; sh_sh[tid] = g_bnshift[tid]; }
    __syncthreads();

    const size_t qbase = (size_t)b * T_ * THREE_DH + h * DK_;
    const size_t vbase = qbase + 2 * DH_;
    const size_t drow0 = (size_t)(b * 512 + h * 64) * 1024;

    for (int t0 = 0; t0 < T_; t0 += 32) {
#pragma unroll
        for (int i = 0; i < 8; i++) {
            int idx = tid + i * 256;       // 0..2047
            int tt = idx >> 6, ch = idx & 63;
            q_sh[tt * 65 + ch] = g_G[qbase + (size_t)(t0 + tt) * THREE_DH + ch];
            v_sh[tt * 65 + ch] = g_G[vbase + (size_t)(t0 + tt) * THREE_DH + ch];
        }
        __syncthreads();

        const int t = t0 + lane;
        float qr[64];
#pragma unroll
        for (int d = 0; d < 64; d++) qr[d] = q_sh[lane * 65 + d];
        const float s_t = S_sh[t];

        float acc[8];
#pragma unroll
        for (int j = 0; j < 8; j++) acc[j] = 0.f;
#pragma unroll
        for (int d = 0; d < 64; d++) {
            float qd = qr[d];
            float4 c0 = *(const float4*)&ctx_sh[d * 64 + w * 8];
            float4 c1 = *(const float4*)&ctx_sh[d * 64 + w * 8 + 4];
            acc[0] += qd * c0.x; acc[1] += qd * c0.y;
            acc[2] += qd * c0.z; acc[3] += qd * c0.w;
            acc[4] += qd * c1.x; acc[5] += qd * c1.y;
            acc[6] += qd * c1.z; acc[7] += qd * c1.w;
        }
#pragma unroll
        for (int j = 0; j < 8; j++) {
            int e = w * 8 + j;
            float vv = v_sh[lane * 65 + e];
            g_D[drow0 + (size_t)e * 1024 + t] = acc[j] + vv * s_t * sc_sh[e] + sh_sh[e];
        }
        __syncthreads();
    }
}

// ---------------------------------------------------------------
// K5b: out[b] = Wout(512x512) @ D_b(512x1024) + bout  (NN SGEMM)
// grid (8, 4, 8), 256 threads
// ---------------------------------------------------------------
__global__ void __launch_bounds__(256) out_gemm_kernel(const float* __restrict__ A,
                                                       const float* __restrict__ bias,
                                                       float* __restrict__ C) {
    __shared__ float As[16][128];
    __shared__ float Bs[16][128];
    const int b = blockIdx.z;
    const int bm = blockIdx.y * 128;     // o
    const int bn = blockIdx.x * 128;     // t
    const int tid = threadIdx.x;
    const int tm = tid >> 4, tn = tid & 15;

    float acc[8][8];
#pragma unroll
    for (int i = 0; i < 8; i++)
#pragma unroll
        for (int j = 0; j < 8; j++) acc[i][j] = 0.f;

    for (int k0 = 0; k0 < 512; k0 += 16) {
#pragma unroll
        for (int i = 0; i < 2; i++) {
            int idx = tid * 2 + i;          // 0..511
            int row = idx >> 2;
            int kc  = (idx & 3) * 4;
            float4 a = *(const float4*)(A + (size_t)(bm + row) * 512 + k0 + kc);
            As[kc + 0][row] = a.x; As[kc + 1][row] = a.y;
            As[kc + 2][row] = a.z; As[kc + 3][row] = a.w;
            int kr  = idx >> 5;             // 0..15
            int col = (idx & 31) * 4;       // 0..124
            float4 bb = *(const float4*)(g_D + (size_t)(b * 512 + k0 + kr) * 1024 + bn + col);
            *(float4*)&Bs[kr][col] = bb;
        }
        __syncthreads();
#pragma unroll
        for (int kk = 0; kk < 16; kk++) {
            float4 a0 = *(const float4*)&As[kk][tm * 8];
            float4 a1 = *(const float4*)&As[kk][tm * 8 + 4];
            float4 b0 = *(const float4*)&Bs[kk][tn * 8];
            float4 b1 = *(const float4*)&Bs[kk][tn * 8 + 4];
            float ra[8] = {a0.x, a0.y, a0.z, a0.w, a1.x, a1.y, a1.z, a1.w};
            float rb[8] = {b0.x, b0.y, b0.z, b0.w, b1.x, b1.y, b1.z, b1.w};
#pragma unroll
            for (int i = 0; i < 8; i++)
#pragma unroll
                for (int j = 0; j < 8; j++) acc[i][j] += ra[i] * rb[j];
        }
        __syncthreads();
    }
#pragma unroll
    for (int i = 0; i < 8; i++) {
        float bo = bias[bm + tm * 8 + i];
        float* crow = C + (size_t)(b * 512 + bm + tm * 8 + i) * 1024 + bn + tn * 8;
#pragma unroll
        for (int j = 0; j < 8; j += 4) {
            float4 v = make_float4(acc[i][j] + bo, acc[i][j + 1] + bo,
                                   acc[i][j + 2] + bo, acc[i][j + 3] + bo);
            *(float4*)(crow + j) = v;
        }
    }
}

// ---------------------------------------------------------------
extern "C" void kernel_launch(void* const* d_in, const int* in_sizes, int n_in,
                              void* d_out, int out_size) {
    const float* x      = (const float*)d_in[0];  // (8,1024,512)
    const float* Wqkv   = (const float*)d_in[1];  // (1536,512)
    const float* Wout   = (const float*)d_in[2];  // (512,512)
    const float* bout   = (const float*)d_in[3];  // (512,)
    const float* relpos = (const float*)d_in[4];  // (63,64)
    const float* gamma  = (const float*)d_in[5];  // (64,)
    const float* beta   = (const float*)d_in[6];  // (64,)
    float* out = (float*)d_out;                    // (8,512,1024)

    prep_kernel<<<1024, 64>>>(relpos);
    qkv_gemm_kernel<<<dim3(12, 64), 256>>>(x, Wqkv);
    ksoftmax_kernel<<<256, 256>>>();
    context_kernel<<<64, 256>>>();
    s_bn_kernel<<<64, 256>>>();
    bn_finalize_kernel<<<1, 64>>>(gamma, beta);
    compute_d_kernel<<<64, 256>>>();
    out_gemm_kernel<<<dim3(8, 4, 8), 256>>>(Wout, bout, out);
}

// round 3
// speedup vs baseline: 2.6929x; 2.6929x over previous
#include <cuda_runtime.h>
#include <math.h>

// Problem constants
#define B_       8
#define T_       1024
#define DIM_     512
#define H_       8
#define DK_      64
#define L_       32
#define DH_      512
#define THREE_DH 1536
#define NH_      64          // B_*H_
#define DOUT_    512
#define EPS_     1e-5f

// -------- scratch (static __device__; no runtime allocation) --------
__device__ float g_G[(size_t)8192 * 1536];   // qkv: row = b*T+t, col o: [0,512)=q [512,1024)=k(raw) [1024,1536)=v
__device__ float g_D[(size_t)4096 * 1024];   // pre-output: row = b*512 + (h*64+e), col t
__device__ float g_ctx[NH_ * DK_ * DK_];     // UNNORMALIZED context[n][d][e] (atomic-accumulated)
__device__ float g_S[NH_ * T_];              // S[n][t]
__device__ float g_Psum[T_ * DK_];           // band-summed rel positions
__device__ float g_ksum[NH_ * DK_];          // softmax denominators (atomic-accumulated)
__device__ float g_bnsum[DK_];
__device__ float g_bnsumsq[DK_];
__device__ float g_bnscale[DK_];
__device__ float g_bnshift[DK_];

// ---------------- tf32 helpers ----------------
__device__ __forceinline__ unsigned f2tf(float v) {
    unsigned r; asm("cvt.rna.tf32.f32 %0, %1;" : "=r"(r) : "f"(v)); return r;
}
// smem layout for mma tiles: element (k, m) -> k*136 + (m ^ ((k>>2)<<2))
// stride 136 == 8 mod 32 -> conflict-free fragment loads; kq-XOR -> conflict-free transposed stores
__device__ __forceinline__ int swz(int k, int m) {
    return k * 136 + (m ^ (((k >> 2) & 7) << 2));
}
__device__ __forceinline__ void mma_tf32(float c[4], const unsigned a[4], const unsigned b[2]) {
    asm volatile(
        "mma.sync.aligned.m16n8k8.row.col.f32.tf32.tf32.f32 "
        "{%0,%1,%2,%3}, {%4,%5,%6,%7}, {%8,%9}, {%0,%1,%2,%3};\n"
        : "+f"(c[0]), "+f"(c[1]), "+f"(c[2]), "+f"(c[3])
        : "r"(a[0]), "r"(a[1]), "r"(a[2]), "r"(a[3]), "r"(b[0]), "r"(b[1]));
}

// ---------------------------------------------------------------
// Prep: Psum + zero all accumulators (ctx, ksum, bn). grid 1024 x 64
// ---------------------------------------------------------------
__global__ void __launch_bounds__(64) prep_kernel(const float* __restrict__ relpos) {
    const int t = blockIdx.x;
    const int d = threadIdx.x;
    int rlo = max(0, (L_ - 1) - t);
    int rhi = min(2 * L_ - 2, (T_ - 1) + (L_ - 1) - t);
    float s = 0.f;
    for (int r = rlo; r <= rhi; r++) s += relpos[r * DK_ + d];
    g_Psum[t * DK_ + d] = s;

    // zero g_ctx: 262144 floats / 1024 blocks = 256 per block
    for (int i = d; i < 256; i += 64) g_ctx[blockIdx.x * 256 + i] = 0.f;
    if (blockIdx.x < NH_) g_ksum[blockIdx.x * DK_ + d] = 0.f;
    if (blockIdx.x == 0) { g_bnsum[d] = 0.f; g_bnsumsq[d] = 0.f; }
}

// ---------------------------------------------------------------
// K1: G = x(8192x512) * Wqkv^T(512x1536)  via tf32 mma.sync
// block tile 128x128, K-chunk 32, 8 warps (2x4), warp tile 64x32
// grid (12, 64), 256 threads
// ---------------------------------------------------------------
__global__ void __launch_bounds__(256) qkv_gemm_kernel(const float* __restrict__ A,
                                                       const float* __restrict__ Bw) {
    __shared__ __align__(16) unsigned As[32 * 136];
    __shared__ __align__(16) unsigned Bs[32 * 136];
    const int bm = blockIdx.y * 128;
    const int bn = blockIdx.x * 128;
    const int tid = threadIdx.x;
    const int wid = tid >> 5, lane = tid & 31;
    const int g = lane >> 2, tig = lane & 3;
    const int wm = (wid >> 2) * 64, wn = (wid & 3) * 32;

    float c[4][4][4];
#pragma unroll
    for (int i = 0; i < 4; i++)
#pragma unroll
        for (int j = 0; j < 4; j++)
#pragma unroll
            for (int r = 0; r < 4; r++) c[i][j][r] = 0.f;

    for (int k0 = 0; k0 < 512; k0 += 32) {
#pragma unroll
        for (int j = 0; j < 4; j++) {
            int idx = tid + j * 256;        // 0..1023
            int row = idx >> 3;             // 0..127
            int kq  = idx & 7;              // 0..7
            float4 a = *(const float4*)(A + (size_t)(bm + row) * 512 + k0 + kq * 4);
            As[swz(kq * 4 + 0, row)] = f2tf(a.x);
            As[swz(kq * 4 + 1, row)] = f2tf(a.y);
            As[swz(kq * 4 + 2, row)] = f2tf(a.z);
            As[swz(kq * 4 + 3, row)] = f2tf(a.w);
            float4 b = *(const float4*)(Bw + (size_t)(bn + row) * 512 + k0 + kq * 4);
            Bs[swz(kq * 4 + 0, row)] = f2tf(b.x);
            Bs[swz(kq * 4 + 1, row)] = f2tf(b.y);
            Bs[swz(kq * 4 + 2, row)] = f2tf(b.z);
            Bs[swz(kq * 4 + 3, row)] = f2tf(b.w);
        }
        __syncthreads();
#pragma unroll
        for (int ks = 0; ks < 4; ks++) {
            const int kk = ks * 8;
            unsigned af[4][4], bf[4][2];
#pragma unroll
            for (int mt = 0; mt < 4; mt++) {
                int R = wm + mt * 16 + g;
                af[mt][0] = As[swz(kk + tig,     R)];
                af[mt][1] = As[swz(kk + tig,     R + 8)];
                af[mt][2] = As[swz(kk + tig + 4, R)];
                af[mt][3] = As[swz(kk + tig + 4, R + 8)];
            }
#pragma unroll
            for (int nt = 0; nt < 4; nt++) {
                int Cn = wn + nt * 8 + g;
                bf[nt][0] = Bs[swz(kk + tig,     Cn)];
                bf[nt][1] = Bs[swz(kk + tig + 4, Cn)];
            }
#pragma unroll
            for (int mt = 0; mt < 4; mt++)
#pragma unroll
                for (int nt = 0; nt < 4; nt++) mma_tf32(c[mt][nt], af[mt], bf[nt]);
        }
        __syncthreads();
    }
#pragma unroll
    for (int mt = 0; mt < 4; mt++)
#pragma unroll
        for (int nt = 0; nt < 4; nt++) {
            int row0 = bm + wm + mt * 16 + g;
            int col  = bn + wn + nt * 8 + tig * 2;
            *(float2*)(g_G + (size_t)row0 * THREE_DH + col) =
                make_float2(c[mt][nt][0], c[mt][nt][1]);
            *(float2*)(g_G + (size_t)(row0 + 8) * THREE_DH + col) =
                make_float2(c[mt][nt][2], c[mt][nt][3]);
        }
}

// ---------------------------------------------------------------
// K2: fused exp + unnormalized context + ksum partials.
// ctx_part[n][d][e] += sum_t exp(k[d,t]) * v[e,t]; ksum[n][d] += sum exp.
// grid (8 tchunks, 64 n), 256 threads
// ---------------------------------------------------------------
__global__ void __launch_bounds__(256) context_kernel() {
    const int tc = blockIdx.x;           // 0..7, 128 t each
    const int n  = blockIdx.y;
    const int b = n >> 3, h = n & 7;
    __shared__ float sk[8][64];
    __shared__ float sv[8][64];
    __shared__ float ksum_sh[64];
    const int tid = threadIdx.x;
    if (tid < 64) ksum_sh[tid] = 0.f;
    __syncthreads();

    const int td = tid & 15, te = tid >> 4;
    const int idx0 = tid * 2;
    const int tt0 = idx0 >> 6;           // 0..7 (fixed per thread)
    const int ch0 = idx0 & 63;           // even

    float acc[4][4];
#pragma unroll
    for (int i = 0; i < 4; i++)
#pragma unroll
        for (int j = 0; j < 4; j++) acc[i][j] = 0.f;
    float ks0 = 0.f, ks1 = 0.f;

    const size_t rowoff_k = (size_t)DH_ + h * DK_ + ch0;
    const size_t rowoff_v = rowoff_k + DH_;

    const int tbase = tc * 128;
    for (int t0 = tbase; t0 < tbase + 128; t0 += 8) {
        size_t row = (size_t)(b * T_ + t0 + tt0) * THREE_DH;
        float2 kr = *(const float2*)(g_G + row + rowoff_k);
        float2 vr = *(const float2*)(g_G + row + rowoff_v);
        float e0 = __expf(kr.x), e1 = __expf(kr.y);
        ks0 += e0; ks1 += e1;
        *(float2*)&sk[tt0][ch0] = make_float2(e0, e1);
        *(float2*)&sv[tt0][ch0] = vr;
        __syncthreads();
#pragma unroll
        for (int tt = 0; tt < 8; tt++) {
            float4 ra = *(const float4*)&sk[tt][td * 4];
            float4 rb = *(const float4*)&sv[tt][te * 4];
            float a4[4] = {ra.x, ra.y, ra.z, ra.w};
            float b4[4] = {rb.x, rb.y, rb.z, rb.w};
#pragma unroll
            for (int i = 0; i < 4; i++)
#pragma unroll
                for (int j = 0; j < 4; j++) acc[i][j] += a4[i] * b4[j];
        }
        __syncthreads();
    }
    atomicAdd(&ksum_sh[ch0], ks0);
    atomicAdd(&ksum_sh[ch0 + 1], ks1);
    __syncthreads();
    if (tid < 64) atomicAdd(&g_ksum[n * DK_ + tid], ksum_sh[tid]);
#pragma unroll
    for (int i = 0; i < 4; i++)
#pragma unroll
        for (int j = 0; j < 4; j++)
            atomicAdd(&g_ctx[(n * DK_ + td * 4 + i) * DK_ + te * 4 + j], acc[i][j]);
}

// ---------------------------------------------------------------
// K3: S[n][t] = sum_d q[n,d,t]*Psum[t,d]; BN partial sums of rel = v*S
// grid (4 tchunks, 64 n), 256 threads
// ---------------------------------------------------------------
__global__ void __launch_bounds__(256) s_bn_kernel() {
    const int tc = blockIdx.x;           // 0..3, 256 t each
    const int n  = blockIdx.y;
    const int b = n >> 3, h = n & 7;
    const int tid = threadIdx.x;
    const int w = tid >> 5, lane = tid & 31;
    __shared__ float S_sh[256];
    const size_t qoff = (size_t)h * DK_;
    const int tbase = tc * 256;

    for (int tl = w; tl < 256; tl += 8) {
        const int t = tbase + tl;
        const float* qrow = g_G + (size_t)(b * T_ + t) * THREE_DH + qoff;
        const float* prow = g_Psum + t * DK_;
        float v = qrow[lane] * prow[lane] + qrow[lane + 32] * prow[lane + 32];
#pragma unroll
        for (int o = 16; o > 0; o >>= 1) v += __shfl_xor_sync(0xffffffff, v, o);
        if (lane == 0) { S_sh[tl] = v; g_S[n * T_ + t] = v; }
    }
    __syncthreads();

    const int e = tid & 63, ts = tid >> 6;
    const size_t voff = (size_t)2 * DH_ + h * DK_ + e;
    float sum = 0.f, sq = 0.f;
    for (int tl = ts; tl < 256; tl += 4) {
        float vv = g_G[(size_t)(b * T_ + tbase + tl) * THREE_DH + voff];
        float r = vv * S_sh[tl];
        sum += r; sq += r * r;
    }
    __shared__ float red[4][64];
    red[ts][e] = sum;
    __syncthreads();
    if (ts == 0) atomicAdd(&g_bnsum[e], red[0][e] + red[1][e] + red[2][e] + red[3][e]);
    __syncthreads();
    red[ts][e] = sq;
    __syncthreads();
    if (ts == 0) atomicAdd(&g_bnsumsq[e], red[0][e] + red[1][e] + red[2][e] + red[3][e]);
}

// ---------------------------------------------------------------
// K4: finalize BN affine params. 1 block x 64 threads
// ---------------------------------------------------------------
__global__ void __launch_bounds__(64) bn_finalize_kernel(const float* __restrict__ gamma,
                                                         const float* __restrict__ beta) {
    const int e = threadIdx.x;
    const float cnt = (float)(NH_ * T_);
    float mu = g_bnsum[e] / cnt;
    float var = g_bnsumsq[e] / cnt - mu * mu;
    var = fmaxf(var, 0.f);
    float sc = gamma[e] * rsqrtf(var + EPS_);
    g_bnscale[e] = sc;
    g_bnshift[e] = beta[e] - mu * sc;
}

// ---------------------------------------------------------------
// K5a: D[b*512+h*64+e][t] = sum_d (ctx[n][d][e]/ksum[n][d])*q[n,d,t] + bn(v*S)
// grid (4 tchunks, 64 n), 256 threads; warp w owns e = w*8..w*8+7, lanes over t
// ---------------------------------------------------------------
__global__ void __launch_bounds__(256) compute_d_kernel() {
    const int tc = blockIdx.x;           // 0..3
    const int n  = blockIdx.y;
    const int b = n >> 3, h = n & 7;
    const int tid = threadIdx.x;
    const int w = tid >> 5, lane = tid & 31;

    __shared__ float ctx_sh[64 * 64];
    __shared__ float q_sh[32 * 65];
    __shared__ float v_sh[32 * 65];
    __shared__ float S_sh[256];
    __shared__ float sc_sh[64], sh_sh[64], rcp_sh[64];

    if (tid < 64) {
        sc_sh[tid] = g_bnscale[tid];
        sh_sh[tid] = g_bnshift[tid];
        rcp_sh[tid] = 1.f / g_ksum[n * DK_ + tid];
    }
    __syncthreads();
    for (int i = tid; i < 4096; i += 256) ctx_sh[i] = g_ctx[n * 4096 + i] * rcp_sh[i >> 6];
    for (int i = tid; i < 256; i += 256) S_sh[i] = g_S[n * T_ + tc * 256 + i];
    __syncthreads();

    const size_t qoff = (size_t)h * DK_;
    const size_t voff = qoff + 2 * DH_;
    const size_t drow0 = (size_t)(b * 512 + h * 64) * 1024;
    const int tbase = tc * 256;

    for (int t0 = tbase; t0 < tbase + 256; t0 += 32) {
#pragma unroll
        for (int i = 0; i < 8; i++) {
            int idx = tid + i * 256;       // 0..2047
            int tt = idx >> 6, ch = idx & 63;
            size_t row = (size_t)(b * T_ + t0 + tt) * THREE_DH;
            q_sh[tt * 65 + ch] = g_G[row + qoff + ch];
            v_sh[tt * 65 + ch] = g_G[row + voff + ch];
        }
        __syncthreads();

        const int t = t0 + lane;
        float qr[64];
#pragma unroll
        for (int d = 0; d < 64; d++) qr[d] = q_sh[lane * 65 + d];
        const float s_t = S_sh[t - tbase];

        float acc[8];
#pragma unroll
        for (int j = 0; j < 8; j++) acc[j] = 0.f;
#pragma unroll
        for (int d = 0; d < 64; d++) {
            float qd = qr[d];
            float4 c0 = *(const float4*)&ctx_sh[d * 64 + w * 8];
            float4 c1 = *(const float4*)&ctx_sh[d * 64 + w * 8 + 4];
            acc[0] += qd * c0.x; acc[1] += qd * c0.y;
            acc[2] += qd * c0.z; acc[3] += qd * c0.w;
            acc[4] += qd * c1.x; acc[5] += qd * c1.y;
            acc[6] += qd * c1.z; acc[7] += qd * c1.w;
        }
#pragma unroll
        for (int j = 0; j < 8; j++) {
            int e = w * 8 + j;
            float vv = v_sh[lane * 65 + e];
            g_D[drow0 + (size_t)e * 1024 + t] = acc[j] + vv * s_t * sc_sh[e] + sh_sh[e];
        }
        __syncthreads();
    }
}

// ---------------------------------------------------------------
// K5b: out[b] = Wout(512x512) @ D_b(512x1024) + bout  via tf32 mma.sync
// grid (8 t, 4 o, 8 b), 256 threads
// ---------------------------------------------------------------
__global__ void __launch_bounds__(256) out_gemm_kernel(const float* __restrict__ A,
                                                       const float* __restrict__ bias,
                                                       float* __restrict__ C) {
    __shared__ __align__(16) unsigned As[32 * 136];
    __shared__ __align__(16) unsigned Bs[32 * 136];
    const int b  = blockIdx.z;
    const int bm = blockIdx.y * 128;     // o
    const int bn = blockIdx.x * 128;     // t
    const int tid = threadIdx.x;
    const int wid = tid >> 5, lane = tid & 31;
    const int g = lane >> 2, tig = lane & 3;
    const int wm = (wid >> 2) * 64, wn = (wid & 3) * 32;

    float c[4][4][4];
#pragma unroll
    for (int i = 0; i < 4; i++)
#pragma unroll
        for (int j = 0; j < 4; j++)
#pragma unroll
            for (int r = 0; r < 4; r++) c[i][j][r] = 0.f;

    for (int k0 = 0; k0 < 512; k0 += 32) {
        // A = Wout [o][d] row-major: transpose-store into (k, m) layout
#pragma unroll
        for (int j = 0; j < 4; j++) {
            int idx = tid + j * 256;        // 0..1023
            int row = idx >> 3;
            int kq  = idx & 7;
            float4 a = *(const float4*)(A + (size_t)(bm + row) * 512 + k0 + kq * 4);
            As[swz(kq * 4 + 0, row)] = f2tf(a.x);
            As[swz(kq * 4 + 1, row)] = f2tf(a.y);
            As[swz(kq * 4 + 2, row)] = f2tf(a.z);
            As[swz(kq * 4 + 3, row)] = f2tf(a.w);
        }
        // B = g_D [d][t]: already k-major rows, direct vectorized store
#pragma unroll
        for (int j = 0; j < 4; j++) {
            int idx = tid + j * 256;        // 0..1023
            int k  = idx >> 5;              // 0..31
            int nq = idx & 31;              // 0..31
            float4 v = *(const float4*)(g_D + (size_t)(b * 512 + k0 + k) * 1024 + bn + nq * 4);
            uint4 u = make_uint4(f2tf(v.x), f2tf(v.y), f2tf(v.z), f2tf(v.w));
            *(uint4*)&Bs[swz(k, nq * 4)] = u;
        }
        __syncthreads();
#pragma unroll
        for (int ks = 0; ks < 4; ks++) {
            const int kk = ks * 8;
            unsigned af[4][4], bf[4][2];
#pragma unroll
            for (int mt = 0; mt < 4; mt++) {
                int R = wm + mt * 16 + g;
                af[mt][0] = As[swz(kk + tig,     R)];
                af[mt][1] = As[swz(kk + tig,     R + 8)];
                af[mt][2] = As[swz(kk + tig + 4, R)];
                af[mt][3] = As[swz(kk + tig + 4, R + 8)];
            }
#pragma unroll
            for (int nt = 0; nt < 4; nt++) {
                int Cn = wn + nt * 8 + g;
                bf[nt][0] = Bs[swz(kk + tig,     Cn)];
                bf[nt][1] = Bs[swz(kk + tig + 4, Cn)];
            }
#pragma unroll
            for (int mt = 0; mt < 4; mt++)
#pragma unroll
                for (int nt = 0; nt < 4; nt++) mma_tf32(c[mt][nt], af[mt], bf[nt]);
        }
        __syncthreads();
    }
#pragma unroll
    for (int mt = 0; mt < 4; mt++)
#pragma unroll
        for (int nt = 0; nt < 4; nt++) {
            int row0 = bm + wm + mt * 16 + g;
            int col  = bn + wn + nt * 8 + tig * 2;
            float bo0 = bias[row0];
            float bo8 = bias[row0 + 8];
            *(float2*)(C + (size_t)(b * 512 + row0) * 1024 + col) =
                make_float2(c[mt][nt][0] + bo0, c[mt][nt][1] + bo0);
            *(float2*)(C + (size_t)(b * 512 + row0 + 8) * 1024 + col) =
                make_float2(c[mt][nt][2] + bo8, c[mt][nt][3] + bo8);
        }
}

// ---------------------------------------------------------------
extern "C" void kernel_launch(void* const* d_in, const int* in_sizes, int n_in,
                              void* d_out, int out_size) {
    const float* x      = (const float*)d_in[0];  // (8,1024,512)
    const float* Wqkv   = (const float*)d_in[1];  // (1536,512)
    const float* Wout   = (const float*)d_in[2];  // (512,512)
    const float* bout   = (const float*)d_in[3];  // (512,)
    const float* relpos = (const float*)d_in[4];  // (63,64)
    const float* gamma  = (const float*)d_in[5];  // (64,)
    const float* beta   = (const float*)d_in[6];  // (64,)
    float* out = (float*)d_out;                    // (8,512,1024)

    prep_kernel<<<1024, 64>>>(relpos);
    qkv_gemm_kernel<<<dim3(12, 64), 256>>>(x, Wqkv);
    context_kernel<<<dim3(8, 64), 256>>>();
    s_bn_kernel<<<dim3(4, 64), 256>>>();
    bn_finalize_kernel<<<1, 64>>>(gamma, beta);
    compute_d_kernel<<<dim3(4, 64), 256>>>();
    out_gemm_kernel<<<dim3(8, 4, 8), 256>>>(Wout, bout, out);
}

// round 15
// speedup vs baseline: 3.1548x; 1.1715x over previous
#include <cuda_runtime.h>
#include <math.h>

// Problem constants
#define B_       8
#define T_       1024
#define DIM_     512
#define H_       8
#define DK_      64
#define L_       32
#define DH_      512
#define THREE_DH 1536
#define NH_      64          // B_*H_
#define DOUT_    512
#define EPS_     1e-5f

// -------- scratch (static __device__; no runtime allocation) --------
__device__ float g_G[(size_t)8192 * 1536];   // qkv: row = b*T+t, col: [0,512)=q [512,1024)=k [1024,1536)=v
__device__ float g_D[(size_t)4096 * 1024];   // pre-output: row = b*512 + (h*64+e), col t
__device__ float g_ctx[NH_ * DK_ * DK_];     // UNNORMALIZED context[n][d][e] (atomic)
__device__ float g_S[NH_ * T_];              // S[n][t] (atomic-accumulated in qkv epilogue)
__device__ float g_Psum[T_ * DK_];           // band-summed rel positions
__device__ float g_ksum[NH_ * DK_];          // softmax denominators (atomic)
__device__ float g_bnsum[DK_];
__device__ float g_bnsumsq[DK_];
__device__ float g_bnscale[DK_];
__device__ float g_bnshift[DK_];

// ---------------- helpers ----------------
__device__ __forceinline__ unsigned f2tf(float v) {
    unsigned r; asm("cvt.rna.tf32.f32 %0, %1;" : "=r"(r) : "f"(v)); return r;
}
__device__ __forceinline__ void mma_tf32(float c[4], const unsigned a[4], const unsigned b[2]) {
    asm volatile(
        "mma.sync.aligned.m16n8k8.row.col.f32.tf32.tf32.f32 "
        "{%0,%1,%2,%3}, {%4,%5,%6,%7}, {%8,%9}, {%0,%1,%2,%3};\n"
        : "+f"(c[0]), "+f"(c[1]), "+f"(c[2]), "+f"(c[3])
        : "r"(a[0]), "r"(a[1]), "r"(a[2]), "r"(a[3]), "r"(b[0]), "r"(b[1]));
}
__device__ __forceinline__ void cp16(float* dst, const float* src) {
    unsigned d = (unsigned)__cvta_generic_to_shared(dst);
    asm volatile("cp.async.ca.shared.global [%0], [%1], 16;\n" :: "r"(d), "l"(src));
}
#define CP_COMMIT() asm volatile("cp.async.commit_group;\n" ::: "memory")
#define CP_WAIT1()  asm volatile("cp.async.wait_group 1;\n" ::: "memory")
#define CP_WAIT0()  asm volatile("cp.async.wait_group 0;\n" ::: "memory")

// ---------------------------------------------------------------
// Prep: Psum + zero accumulators (ctx, ksum, bn, S). grid 1024 x 64
// ---------------------------------------------------------------
__global__ void __launch_bounds__(64) prep_kernel(const float* __restrict__ relpos) {
    const int t = blockIdx.x;
    const int d = threadIdx.x;
    int rlo = max(0, (L_ - 1) - t);
    int rhi = min(2 * L_ - 2, (T_ - 1) + (L_ - 1) - t);
    float s = 0.f;
    for (int r = rlo; r <= rhi; r++) s += relpos[r * DK_ + d];
    g_Psum[t * DK_ + d] = s;

    for (int i = d; i < 256; i += 64) g_ctx[blockIdx.x * 256 + i] = 0.f;
    g_S[blockIdx.x * 64 + d] = 0.f;                       // 1024*64 = 65536 = NH_*T_
    if (blockIdx.x < NH_) g_ksum[blockIdx.x * DK_ + d] = 0.f;
    if (blockIdx.x == 0) { g_bnsum[d] = 0.f; g_bnsumsq[d] = 0.f; }
}

// ---------------------------------------------------------------
// K1: G = x(8192x512) * Wqkv^T(512x1536)  tf32 mma, 2-stage cp.async
// block tile 128x128, K-chunk 16, 8 warps (2x4), warp tile 64x32
// Epilogue (q-col blocks only): S[n][t] += sum_d q*Psum[t,d]
// grid (12, 64), 256 threads
// ---------------------------------------------------------------
__global__ void __launch_bounds__(256) qkv_gemm_kernel(const float* __restrict__ A,
                                                       const float* __restrict__ Bw) {
    // smem: A stages at [0,2560),[2560,5120); B stages at [5120,7680),[7680,10240)
    // (stride 20 per 16-k row; 128 rows). Reused as Psum tile (128x65) in epilogue.
    __shared__ __align__(16) float sm[10240];
    const int bm = blockIdx.y * 128;
    const int bn = blockIdx.x * 128;
    const int tid = threadIdx.x;
    const int wid = tid >> 5, lane = tid & 31;
    const int g = lane >> 2, tig = lane & 3;
    const int wm = (wid >> 2) * 64, wn = (wid & 3) * 32;

    float c[4][4][4];
#pragma unroll
    for (int i = 0; i < 4; i++)
#pragma unroll
        for (int j = 0; j < 4; j++)
#pragma unroll
            for (int r = 0; r < 4; r++) c[i][j][r] = 0.f;

    // prefetch chunk 0 into stage 0
    {
        float* As = sm;
        float* Bs = sm + 5120;
#pragma unroll
        for (int j = 0; j < 2; j++) {
            int idx = tid + j * 256;          // 0..511
            int row = idx >> 2, kq = idx & 3;
            cp16(As + row * 20 + kq * 4, A  + (size_t)(bm + row) * 512 + kq * 4);
            cp16(Bs + row * 20 + kq * 4, Bw + (size_t)(bn + row) * 512 + kq * 4);
        }
        CP_COMMIT();
    }

    for (int ch = 0; ch < 32; ch++) {
        const int cur = ch & 1;
        if (ch < 31) {
            const int nxt = cur ^ 1;
            const int k0 = (ch + 1) * 16;
            float* As = sm + nxt * 2560;
            float* Bs = sm + 5120 + nxt * 2560;
#pragma unroll
            for (int j = 0; j < 2; j++) {
                int idx = tid + j * 256;
                int row = idx >> 2, kq = idx & 3;
                cp16(As + row * 20 + kq * 4, A  + (size_t)(bm + row) * 512 + k0 + kq * 4);
                cp16(Bs + row * 20 + kq * 4, Bw + (size_t)(bn + row) * 512 + k0 + kq * 4);
            }
            CP_COMMIT();
            CP_WAIT1();
        } else {
            CP_WAIT0();
        }
        __syncthreads();
        const float* As = sm + cur * 2560;
        const float* Bs = sm + 5120 + cur * 2560;
#pragma unroll
        for (int ks = 0; ks < 2; ks++) {
            const int kk = ks * 8;
            unsigned af[4][4], bf[4][2];
#pragma unroll
            for (int mt = 0; mt < 4; mt++) {
                int R = wm + mt * 16 + g;
                af[mt][0] = f2tf(As[R * 20 + kk + tig]);
                af[mt][1] = f2tf(As[(R + 8) * 20 + kk + tig]);
                af[mt][2] = f2tf(As[R * 20 + kk + tig + 4]);
                af[mt][3] = f2tf(As[(R + 8) * 20 + kk + tig + 4]);
            }
#pragma unroll
            for (int nt = 0; nt < 4; nt++) {
                int Cn = wn + nt * 8 + g;
                bf[nt][0] = f2tf(Bs[Cn * 20 + kk + tig]);
                bf[nt][1] = f2tf(Bs[Cn * 20 + kk + tig + 4]);
            }
#pragma unroll
            for (int mt = 0; mt < 4; mt++)
#pragma unroll
                for (int nt = 0; nt < 4; nt++) mma_tf32(c[mt][nt], af[mt], bf[nt]);
        }
        __syncthreads();
    }

    // store C
#pragma unroll
    for (int mt = 0; mt < 4; mt++)
#pragma unroll
        for (int nt = 0; nt < 4; nt++) {
            int row0 = bm + wm + mt * 16 + g;
            int col  = bn + wn + nt * 8 + tig * 2;
            *(float2*)(g_G + (size_t)row0 * THREE_DH + col) =
                make_float2(c[mt][nt][0], c[mt][nt][1]);
            *(float2*)(g_G + (size_t)(row0 + 8) * THREE_DH + col) =
                make_float2(c[mt][nt][2], c[mt][nt][3]);
        }

    // ---- S epilogue: only q-column blocks (cols < 512) ----
    if (bn < 512) {
        float* Ps = sm;                          // 128 x 65 = 8320 floats, fits
        const int tb = bm & 1023;                // t-offset within this b
        for (int i = tid; i < 8192; i += 256) {
            int tr = i >> 6, d = i & 63;
            Ps[tr * 65 + d] = g_Psum[(tb + tr) * 64 + d];
        }
        __syncthreads();
        const int bb = bm >> 10;
        const int h  = (bn + wn) >> 6;
        const int dbase = (wn & 32) + tig * 2;
#pragma unroll
        for (int mt = 0; mt < 4; mt++)
#pragma unroll
            for (int hf = 0; hf < 2; hf++) {
                int trow = wm + mt * 16 + g + hf * 8;
                float s = 0.f;
#pragma unroll
                for (int nt = 0; nt < 4; nt++) {
                    int d = dbase + nt * 8;
                    s += c[mt][nt][hf * 2 + 0] * Ps[trow * 65 + d];
                    s += c[mt][nt][hf * 2 + 1] * Ps[trow * 65 + d + 1];
                }
                s += __shfl_xor_sync(0xffffffff, s, 1);
                s += __shfl_xor_sync(0xffffffff, s, 2);
                if (tig == 0)
                    atomicAdd(&g_S[(bb * 8 + h) * T_ + tb + trow], s);
            }
    }
}

// ---------------------------------------------------------------
// K2: fused exp + unnormalized context + ksum partials + BN stats.
// grid (8 tchunks, 64 n), 256 threads
// ---------------------------------------------------------------
__global__ void __launch_bounds__(256) context_kernel() {
    const int tc = blockIdx.x;           // 0..7, 128 t each
    const int n  = blockIdx.y;
    const int b = n >> 3, h = n & 7;
    __shared__ float sk[8][64];
    __shared__ float sv[8][64];
    __shared__ float ksum_sh[64];
    __shared__ float bs_sh[64], bq_sh[64];
    __shared__ float Ssh[128];
    const int tid = threadIdx.x;
    const int tbase = tc * 128;
    if (tid < 64) { ksum_sh[tid] = 0.f; bs_sh[tid] = 0.f; bq_sh[tid] = 0.f; }
    if (tid < 128) Ssh[tid] = g_S[n * T_ + tbase + tid];
    __syncthreads();

    const int td = tid & 15, te = tid >> 4;
    const int idx0 = tid * 2;
    const int tt0 = idx0 >> 6;           // 0..7 (fixed per thread)
    const int ch0 = idx0 & 63;           // even

    float acc[4][4];
#pragma unroll
    for (int i = 0; i < 4; i++)
#pragma unroll
        for (int j = 0; j < 4; j++) acc[i][j] = 0.f;
    float ks0 = 0.f, ks1 = 0.f;
    float lb0 = 0.f, lq0 = 0.f, lb1 = 0.f, lq1 = 0.f;

    const size_t rowoff_k = (size_t)DH_ + h * DK_ + ch0;
    const size_t rowoff_v = rowoff_k + DH_;

    for (int t0 = tbase; t0 < tbase + 128; t0 += 8) {
        size_t row = (size_t)(b * T_ + t0 + tt0) * THREE_DH;
        float2 kr = *(const float2*)(g_G + row + rowoff_k);
        float2 vr = *(const float2*)(g_G + row + rowoff_v);
        float e0 = __expf(kr.x), e1 = __expf(kr.y);
        ks0 += e0; ks1 += e1;
        float st = Ssh[t0 - tbase + tt0];
        float r0 = vr.x * st, r1 = vr.y * st;
        lb0 += r0; lq0 += r0 * r0; lb1 += r1; lq1 += r1 * r1;
        *(float2*)&sk[tt0][ch0] = make_float2(e0, e1);
        *(float2*)&sv[tt0][ch0] = vr;
        __syncthreads();
#pragma unroll
        for (int tt = 0; tt < 8; tt++) {
            float4 ra = *(const float4*)&sk[tt][td * 4];
            float4 rb = *(const float4*)&sv[tt][te * 4];
            float a4[4] = {ra.x, ra.y, ra.z, ra.w};
            float b4[4] = {rb.x, rb.y, rb.z, rb.w};
#pragma unroll
            for (int i = 0; i < 4; i++)
#pragma unroll
                for (int j = 0; j < 4; j++) acc[i][j] += a4[i] * b4[j];
        }
        __syncthreads();
    }
    atomicAdd(&ksum_sh[ch0], ks0);
    atomicAdd(&ksum_sh[ch0 + 1], ks1);
    atomicAdd(&bs_sh[ch0], lb0);
    atomicAdd(&bs_sh[ch0 + 1], lb1);
    atomicAdd(&bq_sh[ch0], lq0);
    atomicAdd(&bq_sh[ch0 + 1], lq1);
    __syncthreads();
    if (tid < 64) {
        atomicAdd(&g_ksum[n * DK_ + tid], ksum_sh[tid]);
        atomicAdd(&g_bnsum[tid], bs_sh[tid]);
        atomicAdd(&g_bnsumsq[tid], bq_sh[tid]);
    }
#pragma unroll
    for (int i = 0; i < 4; i++)
#pragma unroll
        for (int j = 0; j < 4; j++)
            atomicAdd(&g_ctx[(n * DK_ + td * 4 + i) * DK_ + te * 4 + j], acc[i][j]);
}

// ---------------------------------------------------------------
// K4: finalize BN affine params. 1 block x 64 threads
// ---------------------------------------------------------------
__global__ void __launch_bounds__(64) bn_finalize_kernel(const float* __restrict__ gamma,
                                                         const float* __restrict__ beta) {
    const int e = threadIdx.x;
    const float cnt = (float)(NH_ * T_);
    float mu = g_bnsum[e] / cnt;
    float var = g_bnsumsq[e] / cnt - mu * mu;
    var = fmaxf(var, 0.f);
    float sc = gamma[e] * rsqrtf(var + EPS_);
    g_bnscale[e] = sc;
    g_bnshift[e] = beta[e] - mu * sc;
}

// ---------------------------------------------------------------
// K5a: D[b*512+h*64+e][t] = sum_d (ctx[n][d][e]/ksum[n][d])*q[n,d,t] + bn(v*S)
// grid (4 tchunks, 64 n), 256 threads
// ---------------------------------------------------------------
__global__ void __launch_bounds__(256) compute_d_kernel() {
    const int tc = blockIdx.x;           // 0..3
    const int n  = blockIdx.y;
    const int b = n >> 3, h = n & 7;
    const int tid = threadIdx.x;
    const int w = tid >> 5, lane = tid & 31;

    __shared__ float ctx_sh[64 * 64];
    __shared__ float q_sh[32 * 65];
    __shared__ float v_sh[32 * 65];
    __shared__ float S_sh[256];
    __shared__ float sc_sh[64], sh_sh[64], rcp_sh[64];

    if (tid < 64) {
        sc_sh[tid] = g_bnscale[tid];
        sh_sh[tid] = g_bnshift[tid];
        rcp_sh[tid] = 1.f / g_ksum[n * DK_ + tid];
    }
    __syncthreads();
    for (int i = tid; i < 4096; i += 256) ctx_sh[i] = g_ctx[n * 4096 + i] * rcp_sh[i >> 6];
    for (int i = tid; i < 256; i += 256) S_sh[i] = g_S[n * T_ + tc * 256 + i];
    __syncthreads();

    const size_t qoff = (size_t)h * DK_;
    const size_t voff = qoff + 2 * DH_;
    const size_t drow0 = (size_t)(b * 512 + h * 64) * 1024;
    const int tbase = tc * 256;

    for (int t0 = tbase; t0 < tbase + 256; t0 += 32) {
#pragma unroll
        for (int i = 0; i < 8; i++) {
            int idx = tid + i * 256;       // 0..2047
            int tt = idx >> 6, ch = idx & 63;
            size_t row = (size_t)(b * T_ + t0 + tt) * THREE_DH;
            q_sh[tt * 65 + ch] = g_G[row + qoff + ch];
            v_sh[tt * 65 + ch] = g_G[row + voff + ch];
        }
        __syncthreads();

        const int t = t0 + lane;
        float qr[64];
#pragma unroll
        for (int d = 0; d < 64; d++) qr[d] = q_sh[lane * 65 + d];
        const float s_t = S_sh[t - tbase];

        float acc[8];
#pragma unroll
        for (int j = 0; j < 8; j++) acc[j] = 0.f;
#pragma unroll
        for (int d = 0; d < 64; d++) {
            float qd = qr[d];
            float4 c0 = *(const float4*)&ctx_sh[d * 64 + w * 8];
            float4 c1 = *(const float4*)&ctx_sh[d * 64 + w * 8 + 4];
            acc[0] += qd * c0.x; acc[1] += qd * c0.y;
            acc[2] += qd * c0.z; acc[3] += qd * c0.w;
            acc[4] += qd * c1.x; acc[5] += qd * c1.y;
            acc[6] += qd * c1.z; acc[7] += qd * c1.w;
        }
#pragma unroll
        for (int j = 0; j < 8; j++) {
            int e = w * 8 + j;
            float vv = v_sh[lane * 65 + e];
            g_D[drow0 + (size_t)e * 1024 + t] = acc[j] + vv * s_t * sc_sh[e] + sh_sh[e];
        }
        __syncthreads();
    }
}

// ---------------------------------------------------------------
// K5b: out[b] = Wout(512x512) @ D_b(512x1024) + bout  tf32 mma, 2-stage cp.async
// grid (8 t, 4 o, 8 b), 256 threads
// ---------------------------------------------------------------
__global__ void __launch_bounds__(256) out_gemm_kernel(const float* __restrict__ A,
                                                       const float* __restrict__ bias,
                                                       float* __restrict__ C) {
    // A stages: [0,2560),[2560,5120)  (layout [m][k], stride 20)
    // B stages: [5120,7296),[7296,9472) (layout [k][n], stride 136; 16 rows)
    __shared__ __align__(16) float sm[9472];
    const int b  = blockIdx.z;
    const int bm = blockIdx.y * 128;     // o
    const int bn = blockIdx.x * 128;     // t
    const int tid = threadIdx.x;
    const int wid = tid >> 5, lane = tid & 31;
    const int g = lane >> 2, tig = lane & 3;
    const int wm = (wid >> 2) * 64, wn = (wid & 3) * 32;

    float c[4][4][4];
#pragma unroll
    for (int i = 0; i < 4; i++)
#pragma unroll
        for (int j = 0; j < 4; j++)
#pragma unroll
            for (int r = 0; r < 4; r++) c[i][j][r] = 0.f;

    // prefetch chunk 0
    {
        float* As = sm;
        float* Bs = sm + 5120;
#pragma unroll
        for (int j = 0; j < 2; j++) {
            int idx = tid + j * 256;
            int row = idx >> 2, kq = idx & 3;
            cp16(As + row * 20 + kq * 4, A + (size_t)(bm + row) * 512 + kq * 4);
            int k = idx >> 5, nq = idx & 31;
            cp16(Bs + k * 136 + nq * 4, g_D + (size_t)(b * 512 + k) * 1024 + bn + nq * 4);
        }
        CP_COMMIT();
    }

    for (int ch = 0; ch < 32; ch++) {
        const int cur = ch & 1;
        if (ch < 31) {
            const int nxt = cur ^ 1;
            const int k0 = (ch + 1) * 16;
            float* As = sm + nxt * 2560;
            float* Bs = sm + 5120 + nxt * 2176;
#pragma unroll
            for (int j = 0; j < 2; j++) {
                int idx = tid + j * 256;
                int row = idx >> 2, kq = idx & 3;
                cp16(As + row * 20 + kq * 4, A + (size_t)(bm + row) * 512 + k0 + kq * 4);
                int k = idx >> 5, nq = idx & 31;
                cp16(Bs + k * 136 + nq * 4,
                     g_D + (size_t)(b * 512 + k0 + k) * 1024 + bn + nq * 4);
            }
            CP_COMMIT();
            CP_WAIT1();
        } else {
            CP_WAIT0();
        }
        __syncthreads();
        const float* As = sm + cur * 2560;
        const float* Bs = sm + 5120 + cur * 2176;
#pragma unroll
        for (int ks = 0; ks < 2; ks++) {
            const int kk = ks * 8;
            unsigned af[4][4], bf[4][2];
#pragma unroll
            for (int mt = 0; mt < 4; mt++) {
                int R = wm + mt * 16 + g;
                af[mt][0] = f2tf(As[R * 20 + kk + tig]);
                af[mt][1] = f2tf(As[(R + 8) * 20 + kk + tig]);
                af[mt][2] = f2tf(As[R * 20 + kk + tig + 4]);
                af[mt][3] = f2tf(As[(R + 8) * 20 + kk + tig + 4]);
            }
#pragma unroll
            for (int nt = 0; nt < 4; nt++) {
                int Cn = wn + nt * 8 + g;
                bf[nt][0] = f2tf(Bs[(kk + tig) * 136 + Cn]);
                bf[nt][1] = f2tf(Bs[(kk + tig + 4) * 136 + Cn]);
            }
#pragma unroll
            for (int mt = 0; mt < 4; mt++)
#pragma unroll
                for (int nt = 0; nt < 4; nt++) mma_tf32(c[mt][nt], af[mt], bf[nt]);
        }
        __syncthreads();
    }
#pragma unroll
    for (int mt = 0; mt < 4; mt++)
#pragma unroll
        for (int nt = 0; nt < 4; nt++) {
            int row0 = bm + wm + mt * 16 + g;
            int col  = bn + wn + nt * 8 + tig * 2;
            float bo0 = bias[row0];
            float bo8 = bias[row0 + 8];
            *(float2*)(C + (size_t)(b * 512 + row0) * 1024 + col) =
                make_float2(c[mt][nt][0] + bo0, c[mt][nt][1] + bo0);
            *(float2*)(C + (size_t)(b * 512 + row0 + 8) * 1024 + col) =
                make_float2(c[mt][nt][2] + bo8, c[mt][nt][3] + bo8);
        }
}

// ---------------------------------------------------------------
extern "C" void kernel_launch(void* const* d_in, const int* in_sizes, int n_in,
                              void* d_out, int out_size) {
    const float* x      = (const float*)d_in[0];  // (8,1024,512)
    const float* Wqkv   = (const float*)d_in[1];  // (1536,512)
    const float* Wout   = (const float*)d_in[2];  // (512,512)
    const float* bout   = (const float*)d_in[3];  // (512,)
    const float* relpos = (const float*)d_in[4];  // (63,64)
    const float* gamma  = (const float*)d_in[5];  // (64,)
    const float* beta   = (const float*)d_in[6];  // (64,)
    float* out = (float*)d_out;                    // (8,512,1024)

    prep_kernel<<<1024, 64>>>(relpos);
    qkv_gemm_kernel<<<dim3(12, 64), 256>>>(x, Wqkv);
    context_kernel<<<dim3(8, 64), 256>>>();
    bn_finalize_kernel<<<1, 64>>>(gamma, beta);
    compute_d_kernel<<<dim3(4, 64), 256>>>();
    out_gemm_kernel<<<dim3(8, 4, 8), 256>>>(Wout, bout, out);
}